// round 4
// baseline (speedup 1.0000x reference)
#include <cuda_runtime.h>
#include <math.h>
#include <stdint.h>

#define BB 64
#define SS 2048
#define II 512
#define HH 512
#define CLUSTER 8

typedef unsigned long long u64;

// ---- packed fp32x2 helpers (sm_100+) ---------------------------------------
__device__ __forceinline__ u64 ffma2(u64 a, u64 b, u64 c) {
    u64 d;
    asm("fma.rn.f32x2 %0, %1, %2, %3;" : "=l"(d) : "l"(a), "l"(b), "l"(c));
    return d;
}
__device__ __forceinline__ u64 fdup(float x) {
    u64 d;
    asm("mov.b64 %0, {%1, %1};" : "=l"(d) : "f"(x));
    return d;
}
__device__ __forceinline__ void funpack(float& lo, float& hi, u64 v) {
    asm("mov.b64 {%0, %1}, %2;" : "=f"(lo), "=f"(hi) : "l"(v));
}
__device__ __forceinline__ uint32_t smem_u32(const void* p) {
    uint32_t a;
    asm("{ .reg .u64 t; cvta.to.shared.u64 t, %1; cvt.u32.u64 %0, t; }"
        : "=r"(a) : "l"(p));
    return a;
}
__device__ __forceinline__ void mbar_init(uint32_t addr, int cnt) {
    asm volatile("mbarrier.init.shared.b64 [%0], %1;" :: "r"(addr), "r"(cnt) : "memory");
}
__device__ __forceinline__ void mbar_wait(uint32_t addr, int phase) {
    asm volatile(
        "{\n\t.reg .pred P;\n\t"
        "W%=:\n\t"
        "mbarrier.try_wait.parity.acquire.cluster.shared::cta.b64 P, [%0], %1, 0x989680;\n\t"
        "@P bra D%=;\n\t"
        "bra W%=;\n\t"
        "D%=:\n\t}"
        :: "r"(addr), "r"(phase) : "memory");
}

// ---------------------------------------------------------------------------
// Kernel 1: xproj GEMM.  P[m][j] = sum_i X[m][i] * Wx[j][i]
// R2 structure; inner loop uses register-packed f32x2 (Ws j-pairs natural,
// X values duplicated via register movs).
// ---------------------------------------------------------------------------
__global__ __launch_bounds__(256) void xproj_kernel(
    const float* __restrict__ X,
    const float* __restrict__ Wx,
    float* __restrict__ P)
{
    __shared__ float Xs[16][64];
    __shared__ float Ws[16][64];

    const int tid  = threadIdx.x;
    const int m0   = blockIdx.x * 64;
    const int j0   = blockIdx.y * 64;
    const int tx   = tid & 15;        // m micro index
    const int ty   = tid >> 4;        // j micro index
    const int lrow = tid >> 2;        // 0..63 row to load
    const int lk4  = (tid & 3) * 4;   // k offset to load

    const float* xg = X  + (size_t)(m0 + lrow) * II + lk4;
    const float* wg = Wx + (size_t)(j0 + lrow) * II + lk4;

    u64 acc[4][2];
#pragma unroll
    for (int r = 0; r < 4; ++r) { acc[r][0] = 0ull; acc[r][1] = 0ull; }

    for (int kc = 0; kc < II; kc += 16) {
        float4 xa = *(const float4*)(xg + kc);
        float4 wa = *(const float4*)(wg + kc);
        __syncthreads();
        Xs[lk4 + 0][lrow] = xa.x; Xs[lk4 + 1][lrow] = xa.y;
        Xs[lk4 + 2][lrow] = xa.z; Xs[lk4 + 3][lrow] = xa.w;
        Ws[lk4 + 0][lrow] = wa.x; Ws[lk4 + 1][lrow] = wa.y;
        Ws[lk4 + 2][lrow] = wa.z; Ws[lk4 + 3][lrow] = wa.w;
        __syncthreads();
#pragma unroll
        for (int k = 0; k < 16; ++k) {
            const float4 a  = *(const float4*)&Xs[k][tx * 4];
            const u64 b01 = *(const u64*)&Ws[k][ty * 4];
            const u64 b23 = *(const u64*)&Ws[k][ty * 4 + 2];
            const u64 d0 = fdup(a.x), d1 = fdup(a.y), d2 = fdup(a.z), d3 = fdup(a.w);
            acc[0][0] = ffma2(d0, b01, acc[0][0]); acc[0][1] = ffma2(d0, b23, acc[0][1]);
            acc[1][0] = ffma2(d1, b01, acc[1][0]); acc[1][1] = ffma2(d1, b23, acc[1][1]);
            acc[2][0] = ffma2(d2, b01, acc[2][0]); acc[2][1] = ffma2(d2, b23, acc[2][1]);
            acc[3][0] = ffma2(d3, b01, acc[3][0]); acc[3][1] = ffma2(d3, b23, acc[3][1]);
        }
    }

#pragma unroll
    for (int r = 0; r < 4; ++r) {
        float l0, h0v, l1, h1v;
        funpack(l0, h0v, acc[r][0]);
        funpack(l1, h1v, acc[r][1]);
        *(float4*)(P + (size_t)(m0 + tx * 4 + r) * HH + j0 + ty * 4)
            = make_float4(l0, h0v, l1, h1v);
    }
}

// ---------------------------------------------------------------------------
// Kernel 2: persistent recurrent scan with 8-CTA clusters + DSMEM exchange.
// Cluster = batch group bg (blockIdx.x>>3); rank = jg (blockIdx.x&7).
// CTA owns batches [bg*4,+4) and output columns [jg*64,+64).
// Wh slice (64x512) transposed in SMEM with row pad 65 (bank-conflict-free).
// h lives in SMEM as hp[buf][k][b0..b3] (natural b-pairs for f32x2).
// Producers write h_t directly into all 8 cluster CTAs' hp[nb] via
// st.shared::cluster, then signal via mbarriers full[2] (count 8).
// ---------------------------------------------------------------------------
#define WHS_F   (512 * 65)            // 33280 floats
#define HP_OFF  WHS_F
#define HP_BUF  (512 * 4)             // 2048 floats per buffer
#define RED_OFF (HP_OFF + 2 * HP_BUF) // 37376
#define MBAR_F  (RED_OFF + 2048)      // 39424 floats -> byte off 157696 (8-aligned)
#define SCAN_SMEM ((MBAR_F + 8) * 4)  // 157728 bytes

__global__ __launch_bounds__(256, 1) __cluster_dims__(CLUSTER, 1, 1)
void scan_kernel(
    const float* __restrict__ h0,
    const float* __restrict__ Wh,
    const float* __restrict__ bh,
    float* __restrict__ out,        // (B,S,H): holds P on entry, h_t on exit
    float* __restrict__ hlast)      // (B,H)
{
    extern __shared__ float sm[];
    float* Whs = sm;                        // [512][65] Wh^T, padded rows
    float* hp  = sm + HP_OFF;               // [2][512][4]
    float* red = sm + RED_OFF;              // [8][4][64]
    const uint32_t smb   = smem_u32(sm);
    const uint32_t mbar0 = smb + MBAR_F * 4;
    const uint32_t mbar1 = mbar0 + 8;

    const int tid = threadIdx.x;
    const int bg  = blockIdx.x >> 3;
    const int jg  = blockIdx.x & 7;         // == cluster rank
    const int b0  = bg * 4;
    const int j0  = jg * 64;

    if (tid == 0) { mbar_init(mbar0, CLUSTER); mbar_init(mbar1, CLUSTER); }

    // ---- load Wh slice transposed into padded SMEM (once) ----
    {
        const int jl = tid >> 2;             // 0..63
        const int kb = (tid & 3) * 128;
        const float* src = Wh + (size_t)(j0 + jl) * HH + kb;
        for (int kk = 0; kk < 128; kk += 4) {
            float4 v = *(const float4*)(src + kk);
            Whs[(kb + kk + 0) * 65 + jl] = v.x;
            Whs[(kb + kk + 1) * 65 + jl] = v.y;
            Whs[(kb + kk + 2) * 65 + jl] = v.z;
            Whs[(kb + kk + 3) * 65 + jl] = v.w;
        }
    }

    // ---- load h0 into hp[0]: hp[k*4+b] = h0[b0+b][k]  (each CTA full copy) ----
    {
        const int k2 = tid * 2;
#pragma unroll
        for (int bb = 0; bb < 4; ++bb) {
            float2 v = *(const float2*)(h0 + (size_t)(b0 + bb) * HH + k2);
            hp[k2 * 4 + bb]       = v.x;
            hp[(k2 + 1) * 4 + bb] = v.y;
        }
    }
    __syncthreads();
    // mbar init + smem visible cluster-wide before any remote op
    asm volatile("barrier.cluster.arrive.aligned;" ::: "memory");
    asm volatile("barrier.cluster.wait.aligned;" ::: "memory");

    // GEMM mapping: warp w owns k-chunk [w*64,+64); lane = (sk, jb):
    //   jb = lane&15 -> j quad [jb*4,+4); sk = lane>>4 -> k parity
    const int w     = tid >> 5;
    const int lane  = tid & 31;
    const int jb    = lane & 15;
    const int sk    = lane >> 4;
    const int kbase = w * 64;

    // output mapping
    const int rb = tid >> 6;
    const int rj = tid & 63;
    const float bias = bh[j0 + rj];
    const size_t obase = (size_t)(b0 + rb) * SS * HH + j0 + rj;
    // local smem byte addr of this thread's h-slot (buffer 0)
    const uint32_t hslot = smb + (uint32_t)(HP_OFF + (j0 + rj) * 4 + rb) * 4;

    int ph0 = 0, ph1 = 0;

    for (int t = 0; t < SS; ++t) {
        const int b = t & 1;
        const size_t oidx = obase + (size_t)t * HH;
        const float pv = __ldcg(out + oidx);   // pre-activation prefetch

        if (t) {
            if (b) { mbar_wait(mbar1, ph1); ph1 ^= 1; }
            else   { mbar_wait(mbar0, ph0); ph0 ^= 1; }
        }

        // ---- GEMM partial: acc[bpair][j], f32x2, reg-dup weights ----
        const float* hb = hp + b * HP_BUF;
        u64 a00 = 0, a01 = 0, a02 = 0, a03 = 0;
        u64 a10 = 0, a11 = 0, a12 = 0, a13 = 0;
#pragma unroll
        for (int i = 0; i < 32; ++i) {
            const int k = kbase + 2 * i + sk;
            const u64* hq = (const u64*)(hb + k * 4);
            const u64 h01 = hq[0];
            const u64 h23 = hq[1];
            const float* wr = Whs + k * 65 + jb * 4;
            const u64 w0 = fdup(wr[0]);
            const u64 w1 = fdup(wr[1]);
            const u64 w2 = fdup(wr[2]);
            const u64 w3 = fdup(wr[3]);
            a00 = ffma2(h01, w0, a00); a10 = ffma2(h23, w0, a10);
            a01 = ffma2(h01, w1, a01); a11 = ffma2(h23, w1, a11);
            a02 = ffma2(h01, w2, a02); a12 = ffma2(h23, w2, a12);
            a03 = ffma2(h01, w3, a03); a13 = ffma2(h23, w3, a13);
        }

        // ---- fold sub-k halves via shfl, unpack to per-b rows ----
        float r0[4], r1[4], r2[4], r3[4];   // rows b0..b3, 4 j's each
        {
            u64 accs[8] = {a00, a01, a02, a03, a10, a11, a12, a13};
#pragma unroll
            for (int q = 0; q < 8; ++q) {
                float lo, hi;
                funpack(lo, hi, accs[q]);
                lo += __shfl_xor_sync(0xffffffffu, lo, 16);
                hi += __shfl_xor_sync(0xffffffffu, hi, 16);
                if (q < 4) { r0[q] = lo; r1[q] = hi; }
                else       { r2[q - 4] = lo; r3[q - 4] = hi; }
            }
        }
        if (lane < 16) {
            *(float4*)&red[(w * 4 + 0) * 64 + jb * 4] = make_float4(r0[0], r0[1], r0[2], r0[3]);
            *(float4*)&red[(w * 4 + 1) * 64 + jb * 4] = make_float4(r1[0], r1[1], r1[2], r1[3]);
            *(float4*)&red[(w * 4 + 2) * 64 + jb * 4] = make_float4(r2[0], r2[1], r2[2], r2[3]);
            *(float4*)&red[(w * 4 + 3) * 64 + jb * 4] = make_float4(r3[0], r3[1], r3[2], r3[3]);
        }
        __syncthreads();

        // ---- cross-warp reduce, activation, output ----
        float sum = pv + bias;
#pragma unroll
        for (int ww = 0; ww < 8; ++ww)
            sum += red[(ww * 4 + rb) * 64 + rj];
        const float hnew = tanhf(sum);
        __stcg(out + oidx, hnew);

        if (t == SS - 1) {
            hlast[(size_t)(b0 + rb) * HH + j0 + rj] = hnew;
        } else {
            // ---- broadcast h_t slice into all cluster CTAs' hp[nb] ----
            const int nb = b ^ 1;
            const uint32_t loff = hslot + (uint32_t)(nb * HP_BUF) * 4;
#pragma unroll
            for (int r = 0; r < CLUSTER; ++r) {
                uint32_t raddr;
                asm("mapa.shared::cluster.u32 %0, %1, %2;"
                    : "=r"(raddr) : "r"(loff), "r"(r));
                asm volatile("st.shared::cluster.f32 [%0], %1;"
                             :: "r"(raddr), "f"(hnew) : "memory");
            }
            asm volatile("fence.acq_rel.cluster;" ::: "memory");
            __syncthreads();   // also protects red[] for next iteration
            if (tid < CLUSTER) {
                const uint32_t fb = nb ? mbar1 : mbar0;
                uint32_t raddr;
                asm("mapa.shared::cluster.u32 %0, %1, %2;"
                    : "=r"(raddr) : "r"(fb), "r"(tid));
                asm volatile(
                    "mbarrier.arrive.release.cluster.shared::cluster.b64 _, [%0];"
                    :: "r"(raddr) : "memory");
            }
        }
    }

    asm volatile("barrier.cluster.arrive.aligned;" ::: "memory");
    asm volatile("barrier.cluster.wait.aligned;" ::: "memory");
}

// ---------------------------------------------------------------------------
extern "C" void kernel_launch(void* const* d_in, const int* in_sizes, int n_in,
                              void* d_out, int out_size) {
    const float* x   = (const float*)d_in[0];   // (B,S,I)
    const float* h0  = (const float*)d_in[1];   // (B,H)
    const float* Wx  = (const float*)d_in[2];   // (H,I)
    const float* Wh  = (const float*)d_in[3];   // (H,H)
    const float* bh  = (const float*)d_in[4];   // (H,)
    float* out   = (float*)d_out;                          // (B,S,H)
    float* hlast = out + (size_t)BB * SS * HH;             // (B,H)

    cudaFuncSetAttribute(scan_kernel,
                         cudaFuncAttributeMaxDynamicSharedMemorySize, SCAN_SMEM);

    dim3 gg((BB * SS) / 64, HH / 64);   // (2048, 8)
    xproj_kernel<<<gg, 256>>>(x, Wx, out);

    scan_kernel<<<128, 256, SCAN_SMEM>>>(h0, Wh, bh, out, hlast);
}

// round 6
// speedup vs baseline: 2.2104x; 2.2104x over previous
#include <cuda_runtime.h>
#include <math.h>
#include <stdint.h>

#define BB 64
#define SS 2048
#define II 512
#define HH 512

#define NGB 16   // batch groups
#define NGJ 8    // j slices per group
#define BC  4    // batches per group
#define JC  64   // j per slice

typedef unsigned long long u64;

// per-group arrival counters (reset by reset_kernel each launch)
__device__ int g_sync[NGB];

__global__ void reset_kernel() {
    if (threadIdx.x < NGB) g_sync[threadIdx.x] = 0;
}

__device__ __forceinline__ u64 ffma2(u64 a, u64 b, u64 c) {
    u64 d;
    asm("fma.rn.f32x2 %0, %1, %2, %3;" : "=l"(d) : "l"(a), "l"(b), "l"(c));
    return d;
}
__device__ __forceinline__ void funpack(float& lo, float& hi, u64 v) {
    asm("mov.b64 {%0, %1}, %2;" : "=f"(lo), "=f"(hi) : "l"(v));
}

// ---------------------------------------------------------------------------
// Kernel 1: xproj GEMM (verbatim R2).  P[m][j] = sum_i X[m][i] * Wx[j][i]
// ---------------------------------------------------------------------------
__global__ __launch_bounds__(256) void xproj_kernel(
    const float* __restrict__ X,
    const float* __restrict__ Wx,
    float* __restrict__ P)
{
    __shared__ float Xs[16][64];
    __shared__ float Ws[16][64];

    const int tid  = threadIdx.x;
    const int m0   = blockIdx.x * 64;
    const int j0   = blockIdx.y * 64;
    const int tx   = tid & 15;
    const int ty   = tid >> 4;
    const int lrow = tid >> 2;
    const int lk4  = (tid & 3) * 4;

    const float* xg = X  + (size_t)(m0 + lrow) * II + lk4;
    const float* wg = Wx + (size_t)(j0 + lrow) * II + lk4;

    float acc[4][4];
#pragma unroll
    for (int r = 0; r < 4; ++r)
#pragma unroll
        for (int c = 0; c < 4; ++c) acc[r][c] = 0.0f;

    for (int kc = 0; kc < II; kc += 16) {
        float4 xa = *(const float4*)(xg + kc);
        float4 wa = *(const float4*)(wg + kc);
        __syncthreads();
        Xs[lk4 + 0][lrow] = xa.x; Xs[lk4 + 1][lrow] = xa.y;
        Xs[lk4 + 2][lrow] = xa.z; Xs[lk4 + 3][lrow] = xa.w;
        Ws[lk4 + 0][lrow] = wa.x; Ws[lk4 + 1][lrow] = wa.y;
        Ws[lk4 + 2][lrow] = wa.z; Ws[lk4 + 3][lrow] = wa.w;
        __syncthreads();
#pragma unroll
        for (int k = 0; k < 16; ++k) {
            float4 a  = *(const float4*)&Xs[k][tx * 4];
            float4 bq = *(const float4*)&Ws[k][ty * 4];
            acc[0][0] += a.x * bq.x; acc[0][1] += a.x * bq.y;
            acc[0][2] += a.x * bq.z; acc[0][3] += a.x * bq.w;
            acc[1][0] += a.y * bq.x; acc[1][1] += a.y * bq.y;
            acc[1][2] += a.y * bq.z; acc[1][3] += a.y * bq.w;
            acc[2][0] += a.z * bq.x; acc[2][1] += a.z * bq.y;
            acc[2][2] += a.z * bq.z; acc[2][3] += a.z * bq.w;
            acc[3][0] += a.w * bq.x; acc[3][1] += a.w * bq.y;
            acc[3][2] += a.w * bq.z; acc[3][3] += a.w * bq.w;
        }
    }

#pragma unroll
    for (int r = 0; r < 4; ++r) {
        float4 o = make_float4(acc[r][0], acc[r][1], acc[r][2], acc[r][3]);
        *(float4*)(P + (size_t)(m0 + tx * 4 + r) * HH + j0 + ty * 4) = o;
    }
}

// ---------------------------------------------------------------------------
// Kernel 2: persistent recurrent scan (R2 structure/sync verbatim).
// ONLY the inner GEMM changed: k-packed fma.rn.f32x2.
//   Whs2[j][k] = Wh[j0+j][k], j-major rows of 512 k, with 16B-block swizzle
//   kb ^= (j&7) for conflict-free LDS.128.  h stays in R2's hs[b][k] layout.
//   Lane owns j in {lane, lane+32}; accumulators pack (even-k, odd-k).
// ---------------------------------------------------------------------------
#define SCAN_SMEM (64*512*4 + 4*512*4 + 8*4*64*4)   // Whs2 + hs + red = 147456

__global__ __launch_bounds__(256, 1) void scan_kernel(
    const float* __restrict__ h0,
    const float* __restrict__ Wh,
    const float* __restrict__ bh,
    float* __restrict__ out,        // (B,S,H): holds P on entry, h_t on exit
    float* __restrict__ hlast)      // (B,H)
{
    extern __shared__ float sm[];
    float* Whs2 = sm;                 // [64 j][512 k], block-swizzled
    float* hs   = sm + 64 * 512;      // [4][512]
    float* red  = hs + 4 * 512;       // [8][4][64]

    const int tid = threadIdx.x;
    const int bg  = blockIdx.x >> 3;     // 0..15
    const int jg  = blockIdx.x & 7;      // 0..7
    const int b0  = bg * BC;
    const int j0  = jg * JC;

    // ---- load Wh slice j-major with block swizzle (once) ----
    {
        const int jl = tid >> 2;             // 0..63
        const int kb = (tid & 3) * 128;      // k chunk base
        const int sw = (jl & 7) << 2;        // word-offset XOR (16B blocks)
        const float* src = Wh + (size_t)(j0 + jl) * HH + kb;
        float* dst = Whs2 + jl * 512;
        for (int kk = 0; kk < 128; kk += 4) {
            float4 v = *(const float4*)(src + kk);
            *(float4*)(dst + ((kb + kk) ^ sw)) = v;
        }
    }

    // compute mapping: warp = k-chunk, lane covers j and j+32, all 4 b's
    const int w     = tid >> 5;          // 0..7 -> k in [w*64, w*64+64)
    const int lane  = tid & 31;
    const int kbase = w * 64;
    const int swz   = (lane & 7) << 2;   // same for j=lane and j=lane+32
    const float* wrow0 = Whs2 + lane * 512;
    const float* wrow1 = Whs2 + (lane + 32) * 512;

    // reduce / output mapping: one thread per output element
    const int rb = tid >> 6;             // 0..3
    const int rj = tid & 63;             // 0..63
    const float bias = bh[j0 + rj];

    // h-load mapping: 4 rows x 512, 8 floats per thread
    const int hrow = tid >> 6;           // 0..3
    const int hk   = (tid & 63) * 8;     // 0..504

    __syncthreads();

    for (int t = 0; t < SS; ++t) {
        // ---- load h_{t-1} rows into SMEM (bypass L1 for cross-CTA data) ----
        const float* hp = (t == 0)
            ? (h0 + (size_t)(b0 + hrow) * HH + hk)
            : (out + ((size_t)(b0 + hrow) * SS + (t - 1)) * HH + hk);
        float4 hv0 = __ldcg((const float4*)hp);
        float4 hv1 = __ldcg((const float4*)(hp + 4));

        // prefetch this thread's pre-activation P[b,t,j] (independent of h)
        const size_t oidx = ((size_t)(b0 + rb) * SS + t) * HH + j0 + rj;
        const float pv = __ldcg(out + oidx);

        *(float4*)&hs[hrow * 512 + hk]     = hv0;
        *(float4*)&hs[hrow * 512 + hk + 4] = hv1;
        __syncthreads();

        // ---- k-packed f32x2 partial GEMM over this warp's k-chunk ----
        u64 acc[4][2];
#pragma unroll
        for (int b = 0; b < 4; ++b) { acc[b][0] = 0ull; acc[b][1] = 0ull; }

#pragma unroll
        for (int kk = 0; kk < 64; kk += 4) {
            const int k4 = kbase + kk;
            const ulonglong2 wv0 = *(const ulonglong2*)(wrow0 + (k4 ^ swz));
            const ulonglong2 wv1 = *(const ulonglong2*)(wrow1 + (k4 ^ swz));
#pragma unroll
            for (int b = 0; b < 4; ++b) {
                const ulonglong2 hq = *(const ulonglong2*)&hs[b * 512 + k4];
                acc[b][0] = ffma2(hq.x, wv0.x, acc[b][0]);
                acc[b][0] = ffma2(hq.y, wv0.y, acc[b][0]);
                acc[b][1] = ffma2(hq.x, wv1.x, acc[b][1]);
                acc[b][1] = ffma2(hq.y, wv1.y, acc[b][1]);
            }
        }

        // fold (even,odd) halves and publish partials
#pragma unroll
        for (int b = 0; b < 4; ++b) {
            float e0, o0v, e1, o1v;
            funpack(e0, o0v, acc[b][0]);
            funpack(e1, o1v, acc[b][1]);
            red[(w * 4 + b) * 64 + lane]      = e0 + o0v;
            red[(w * 4 + b) * 64 + lane + 32] = e1 + o1v;
        }
        __syncthreads();

        // ---- reduce k-split partials, add P + bias, tanh, write h_t ----
        float sum = pv + bias;
#pragma unroll
        for (int ww = 0; ww < 8; ++ww)
            sum += red[(ww * 4 + rb) * 64 + rj];
        const float hnew = tanhf(sum);
        __stcg(out + oidx, hnew);
        if (t == SS - 1)
            hlast[(size_t)(b0 + rb) * HH + j0 + rj] = hnew;

        // ---- group barrier: release own slice, acquire peers' slices ----
        if (t < SS - 1) {
            __threadfence();
            __syncthreads();
            if (tid == 0) {
                atomicAdd(&g_sync[bg], 1);
                const int target = NGJ * (t + 1);
                while (atomicAdd(&g_sync[bg], 0) < target) { __nanosleep(64); }
                __threadfence();
            }
            __syncthreads();
        }
    }
}

// ---------------------------------------------------------------------------
extern "C" void kernel_launch(void* const* d_in, const int* in_sizes, int n_in,
                              void* d_out, int out_size) {
    const float* x   = (const float*)d_in[0];   // (B,S,I)
    const float* h0  = (const float*)d_in[1];   // (B,H)
    const float* Wx  = (const float*)d_in[2];   // (H,I)
    const float* Wh  = (const float*)d_in[3];   // (H,H)
    const float* bh  = (const float*)d_in[4];   // (H,)
    float* out   = (float*)d_out;                          // (B,S,H)
    float* hlast = out + (size_t)BB * SS * HH;             // (B,H)

    cudaFuncSetAttribute(scan_kernel,
                         cudaFuncAttributeMaxDynamicSharedMemorySize, SCAN_SMEM);

    reset_kernel<<<1, 32>>>();

    dim3 gg((BB * SS) / 64, HH / 64);   // (2048, 8)
    xproj_kernel<<<gg, 256>>>(x, Wx, out);

    scan_kernel<<<128, 256, SCAN_SMEM>>>(h0, Wh, bh, out, hlast);
}

// round 9
// speedup vs baseline: 2.3629x; 1.0690x over previous
#include <cuda_runtime.h>
#include <math.h>
#include <stdint.h>

#define BB 64
#define SS 2048
#define II 512
#define HH 512

#define NGB 16   // batch groups
#define NGJ 8    // j slices per group
#define BC  4    // batches per group
#define JC  64   // j per slice

typedef unsigned long long u64;

// per-group arrival counters (reset by reset_kernel each launch)
__device__ int g_sync[NGB];

__global__ void reset_kernel() {
    if (threadIdx.x < NGB) g_sync[threadIdx.x] = 0;
}

__device__ __forceinline__ u64 ffma2(u64 a, u64 b, u64 c) {
    u64 d;
    asm("fma.rn.f32x2 %0, %1, %2, %3;" : "=l"(d) : "l"(a), "l"(b), "l"(c));
    return d;
}
__device__ __forceinline__ u64 fdup(float x) {
    u64 d;
    asm("mov.b64 %0, {%1, %1};" : "=l"(d) : "f"(x));
    return d;
}
__device__ __forceinline__ void funpack(float& lo, float& hi, u64 v) {
    asm("mov.b64 {%0, %1}, %2;" : "=f"(lo), "=f"(hi) : "l"(v));
}

// ---------------------------------------------------------------------------
// Kernel 1: xproj GEMM, rebuilt.  P[m][j] = sum_i X[m][i] * Wx[j][i]
// 128x128 tile, 256 threads, 8m x 8j per thread via m-packed fma.rn.f32x2:
//   acc[mi][jp] packs j-pair (natural 64-bit LDS from Ws[k][j]);
//   m operand duplicated in a register (ALU mov, parallel pipe).
// ktile 16 staged in SMEM (transposed scalar stores), 2 CTAs/SM overlap.
// ---------------------------------------------------------------------------
__global__ __launch_bounds__(256, 2) void xproj_kernel(
    const float* __restrict__ X,
    const float* __restrict__ Wx,
    float* __restrict__ P)
{
    __shared__ float Xs[16][128];   // [k][m]
    __shared__ float Ws[16][128];   // [k][j]

    const int tid = threadIdx.x;
    const int m0  = blockIdx.x * 128;
    const int j0  = blockIdx.y * 128;
    const int tx  = tid & 15;        // m micro index: rows tx*8..+8
    const int ty  = tid >> 4;        // j micro index: cols ty*8..+8

    const int lrow = tid >> 1;          // 0..127: row to load
    const int lk8  = (tid & 1) * 8;     // 0 or 8: k offset

    const float* xg = X  + (size_t)(m0 + lrow) * II + lk8;
    const float* wg = Wx + (size_t)(j0 + lrow) * II + lk8;

    u64 acc[8][4];
#pragma unroll
    for (int mi = 0; mi < 8; ++mi)
#pragma unroll
        for (int jp = 0; jp < 4; ++jp) acc[mi][jp] = 0ull;

    for (int kc = 0; kc < II; kc += 16) {
        const float4 xa0 = *(const float4*)(xg + kc);
        const float4 xa1 = *(const float4*)(xg + kc + 4);
        const float4 wa0 = *(const float4*)(wg + kc);
        const float4 wa1 = *(const float4*)(wg + kc + 4);
        __syncthreads();
        Xs[lk8 + 0][lrow] = xa0.x; Xs[lk8 + 1][lrow] = xa0.y;
        Xs[lk8 + 2][lrow] = xa0.z; Xs[lk8 + 3][lrow] = xa0.w;
        Xs[lk8 + 4][lrow] = xa1.x; Xs[lk8 + 5][lrow] = xa1.y;
        Xs[lk8 + 6][lrow] = xa1.z; Xs[lk8 + 7][lrow] = xa1.w;
        Ws[lk8 + 0][lrow] = wa0.x; Ws[lk8 + 1][lrow] = wa0.y;
        Ws[lk8 + 2][lrow] = wa0.z; Ws[lk8 + 3][lrow] = wa0.w;
        Ws[lk8 + 4][lrow] = wa1.x; Ws[lk8 + 5][lrow] = wa1.y;
        Ws[lk8 + 6][lrow] = wa1.z; Ws[lk8 + 7][lrow] = wa1.w;
        __syncthreads();
#pragma unroll
        for (int k = 0; k < 16; ++k) {
            float a8[8];
            *(float4*)&a8[0] = *(const float4*)&Xs[k][tx * 8];
            *(float4*)&a8[4] = *(const float4*)&Xs[k][tx * 8 + 4];
            u64 b[4];
            b[0] = *(const u64*)&Ws[k][ty * 8 + 0];
            b[1] = *(const u64*)&Ws[k][ty * 8 + 2];
            b[2] = *(const u64*)&Ws[k][ty * 8 + 4];
            b[3] = *(const u64*)&Ws[k][ty * 8 + 6];
#pragma unroll
            for (int mi = 0; mi < 8; ++mi) {
                const u64 am = fdup(a8[mi]);
                acc[mi][0] = ffma2(am, b[0], acc[mi][0]);
                acc[mi][1] = ffma2(am, b[1], acc[mi][1]);
                acc[mi][2] = ffma2(am, b[2], acc[mi][2]);
                acc[mi][3] = ffma2(am, b[3], acc[mi][3]);
            }
        }
    }

#pragma unroll
    for (int mi = 0; mi < 8; ++mi) {
        float r[8];
#pragma unroll
        for (int jp = 0; jp < 4; ++jp)
            funpack(r[2 * jp], r[2 * jp + 1], acc[mi][jp]);
        float* dst = P + (size_t)(m0 + tx * 8 + mi) * HH + j0 + ty * 8;
        *(float4*)dst       = make_float4(r[0], r[1], r[2], r[3]);
        *(float4*)(dst + 4) = make_float4(r[4], r[5], r[6], r[7]);
    }
}

// ---------------------------------------------------------------------------
// Kernel 2: persistent recurrent scan (verbatim R6 — proven at 8703us).
// ---------------------------------------------------------------------------
#define SCAN_SMEM (64*512*4 + 4*512*4 + 8*4*64*4)   // Whs2 + hs + red = 147456

__global__ __launch_bounds__(256, 1) void scan_kernel(
    const float* __restrict__ h0,
    const float* __restrict__ Wh,
    const float* __restrict__ bh,
    float* __restrict__ out,        // (B,S,H): holds P on entry, h_t on exit
    float* __restrict__ hlast)      // (B,H)
{
    extern __shared__ float sm[];
    float* Whs2 = sm;                 // [64 j][512 k], block-swizzled
    float* hs   = sm + 64 * 512;      // [4][512]
    float* red  = hs + 4 * 512;       // [8][4][64]

    const int tid = threadIdx.x;
    const int bg  = blockIdx.x >> 3;     // 0..15
    const int jg  = blockIdx.x & 7;      // 0..7
    const int b0  = bg * BC;
    const int j0  = jg * JC;

    // ---- load Wh slice j-major with block swizzle (once) ----
    {
        const int jl = tid >> 2;             // 0..63
        const int kb = (tid & 3) * 128;      // k chunk base
        const int sw = (jl & 7) << 2;        // word-offset XOR (16B blocks)
        const float* src = Wh + (size_t)(j0 + jl) * HH + kb;
        float* dst = Whs2 + jl * 512;
        for (int kk = 0; kk < 128; kk += 4) {
            float4 v = *(const float4*)(src + kk);
            *(float4*)(dst + ((kb + kk) ^ sw)) = v;
        }
    }

    // compute mapping: warp = k-chunk, lane covers j and j+32, all 4 b's
    const int w     = tid >> 5;          // 0..7 -> k in [w*64, w*64+64)
    const int lane  = tid & 31;
    const int kbase = w * 64;
    const int swz   = (lane & 7) << 2;   // same for j=lane and j=lane+32
    const float* wrow0 = Whs2 + lane * 512;
    const float* wrow1 = Whs2 + (lane + 32) * 512;

    // reduce / output mapping: one thread per output element
    const int rb = tid >> 6;             // 0..3
    const int rj = tid & 63;             // 0..63
    const float bias = bh[j0 + rj];

    // h-load mapping: 4 rows x 512, 8 floats per thread
    const int hrow = tid >> 6;           // 0..3
    const int hk   = (tid & 63) * 8;     // 0..504

    __syncthreads();

    for (int t = 0; t < SS; ++t) {
        // ---- load h_{t-1} rows into SMEM (bypass L1 for cross-CTA data) ----
        const float* hp = (t == 0)
            ? (h0 + (size_t)(b0 + hrow) * HH + hk)
            : (out + ((size_t)(b0 + hrow) * SS + (t - 1)) * HH + hk);
        float4 hv0 = __ldcg((const float4*)hp);
        float4 hv1 = __ldcg((const float4*)(hp + 4));

        // prefetch this thread's pre-activation P[b,t,j] (independent of h)
        const size_t oidx = ((size_t)(b0 + rb) * SS + t) * HH + j0 + rj;
        const float pv = __ldcg(out + oidx);

        *(float4*)&hs[hrow * 512 + hk]     = hv0;
        *(float4*)&hs[hrow * 512 + hk + 4] = hv1;
        __syncthreads();

        // ---- k-packed f32x2 partial GEMM over this warp's k-chunk ----
        u64 acc[4][2];
#pragma unroll
        for (int b = 0; b < 4; ++b) { acc[b][0] = 0ull; acc[b][1] = 0ull; }

#pragma unroll
        for (int kk = 0; kk < 64; kk += 4) {
            const int k4 = kbase + kk;
            const ulonglong2 wv0 = *(const ulonglong2*)(wrow0 + (k4 ^ swz));
            const ulonglong2 wv1 = *(const ulonglong2*)(wrow1 + (k4 ^ swz));
#pragma unroll
            for (int b = 0; b < 4; ++b) {
                const ulonglong2 hq = *(const ulonglong2*)&hs[b * 512 + k4];
                acc[b][0] = ffma2(hq.x, wv0.x, acc[b][0]);
                acc[b][0] = ffma2(hq.y, wv0.y, acc[b][0]);
                acc[b][1] = ffma2(hq.x, wv1.x, acc[b][1]);
                acc[b][1] = ffma2(hq.y, wv1.y, acc[b][1]);
            }
        }

        // fold (even,odd) halves and publish partials
#pragma unroll
        for (int b = 0; b < 4; ++b) {
            float e0, o0v, e1, o1v;
            funpack(e0, o0v, acc[b][0]);
            funpack(e1, o1v, acc[b][1]);
            red[(w * 4 + b) * 64 + lane]      = e0 + o0v;
            red[(w * 4 + b) * 64 + lane + 32] = e1 + o1v;
        }
        __syncthreads();

        // ---- reduce k-split partials, add P + bias, tanh, write h_t ----
        float sum = pv + bias;
#pragma unroll
        for (int ww = 0; ww < 8; ++ww)
            sum += red[(ww * 4 + rb) * 64 + rj];
        const float hnew = tanhf(sum);
        __stcg(out + oidx, hnew);
        if (t == SS - 1)
            hlast[(size_t)(b0 + rb) * HH + j0 + rj] = hnew;

        // ---- group barrier: release own slice, acquire peers' slices ----
        if (t < SS - 1) {
            __threadfence();
            __syncthreads();
            if (tid == 0) {
                atomicAdd(&g_sync[bg], 1);
                const int target = NGJ * (t + 1);
                while (atomicAdd(&g_sync[bg], 0) < target) { __nanosleep(64); }
                __threadfence();
            }
            __syncthreads();
        }
    }
}

// ---------------------------------------------------------------------------
extern "C" void kernel_launch(void* const* d_in, const int* in_sizes, int n_in,
                              void* d_out, int out_size) {
    const float* x   = (const float*)d_in[0];   // (B,S,I)
    const float* h0  = (const float*)d_in[1];   // (B,H)
    const float* Wx  = (const float*)d_in[2];   // (H,I)
    const float* Wh  = (const float*)d_in[3];   // (H,H)
    const float* bh  = (const float*)d_in[4];   // (H,)
    float* out   = (float*)d_out;                          // (B,S,H)
    float* hlast = out + (size_t)BB * SS * HH;             // (B,H)

    cudaFuncSetAttribute(scan_kernel,
                         cudaFuncAttributeMaxDynamicSharedMemorySize, SCAN_SMEM);

    reset_kernel<<<1, 32>>>();

    dim3 gg((BB * SS) / 128, HH / 128);   // (1024, 4)
    xproj_kernel<<<gg, 256>>>(x, Wx, out);

    scan_kernel<<<128, 256, SCAN_SMEM>>>(h0, Wh, bh, out, hlast);
}

// round 14
// speedup vs baseline: 2.6542x; 1.1233x over previous
#include <cuda_runtime.h>
#include <math.h>
#include <stdint.h>

#define BB 64
#define SS 2048
#define II 512
#define HH 512

#define NGB 16   // batch groups
#define NGJ 8    // j slices per group
#define BC  4    // batches per group
#define JC  64   // j per slice

typedef unsigned long long u64;

// per-group arrival counters (reset by reset_kernel each launch)
__device__ int g_sync[NGB];

__global__ void reset_kernel() {
    if (threadIdx.x < NGB) g_sync[threadIdx.x] = 0;
}

__device__ __forceinline__ u64 ffma2(u64 a, u64 b, u64 c) {
    u64 d;
    asm("fma.rn.f32x2 %0, %1, %2, %3;" : "=l"(d) : "l"(a), "l"(b), "l"(c));
    return d;
}
__device__ __forceinline__ u64 fdup(float x) {
    u64 d;
    asm("mov.b64 %0, {%1, %1};" : "=l"(d) : "f"(x));
    return d;
}
__device__ __forceinline__ void funpack(float& lo, float& hi, u64 v) {
    asm("mov.b64 {%0, %1}, %2;" : "=f"(lo), "=f"(hi) : "l"(v));
}
__device__ __forceinline__ int ld_acq(const int* p) {
    int v;
    asm volatile("ld.global.acquire.gpu.b32 %0, [%1];" : "=r"(v) : "l"(p));
    return v;
}

// ---------------------------------------------------------------------------
// Kernel 1: xproj GEMM (verbatim R9 — proven).  P[m][j] = sum_i X[m][i]*Wx[j][i]
// 128x128 tile, 256 threads, 8m x 8j per thread via m-packed fma.rn.f32x2.
// ---------------------------------------------------------------------------
__global__ __launch_bounds__(256, 2) void xproj_kernel(
    const float* __restrict__ X,
    const float* __restrict__ Wx,
    float* __restrict__ P)
{
    __shared__ float Xs[16][128];   // [k][m]
    __shared__ float Ws[16][128];   // [k][j]

    const int tid = threadIdx.x;
    const int m0  = blockIdx.x * 128;
    const int j0  = blockIdx.y * 128;
    const int tx  = tid & 15;        // m micro index: rows tx*8..+8
    const int ty  = tid >> 4;        // j micro index: cols ty*8..+8

    const int lrow = tid >> 1;          // 0..127: row to load
    const int lk8  = (tid & 1) * 8;     // 0 or 8: k offset

    const float* xg = X  + (size_t)(m0 + lrow) * II + lk8;
    const float* wg = Wx + (size_t)(j0 + lrow) * II + lk8;

    u64 acc[8][4];
#pragma unroll
    for (int mi = 0; mi < 8; ++mi)
#pragma unroll
        for (int jp = 0; jp < 4; ++jp) acc[mi][jp] = 0ull;

    for (int kc = 0; kc < II; kc += 16) {
        const float4 xa0 = *(const float4*)(xg + kc);
        const float4 xa1 = *(const float4*)(xg + kc + 4);
        const float4 wa0 = *(const float4*)(wg + kc);
        const float4 wa1 = *(const float4*)(wg + kc + 4);
        __syncthreads();
        Xs[lk8 + 0][lrow] = xa0.x; Xs[lk8 + 1][lrow] = xa0.y;
        Xs[lk8 + 2][lrow] = xa0.z; Xs[lk8 + 3][lrow] = xa0.w;
        Xs[lk8 + 4][lrow] = xa1.x; Xs[lk8 + 5][lrow] = xa1.y;
        Xs[lk8 + 6][lrow] = xa1.z; Xs[lk8 + 7][lrow] = xa1.w;
        Ws[lk8 + 0][lrow] = wa0.x; Ws[lk8 + 1][lrow] = wa0.y;
        Ws[lk8 + 2][lrow] = wa0.z; Ws[lk8 + 3][lrow] = wa0.w;
        Ws[lk8 + 4][lrow] = wa1.x; Ws[lk8 + 5][lrow] = wa1.y;
        Ws[lk8 + 6][lrow] = wa1.z; Ws[lk8 + 7][lrow] = wa1.w;
        __syncthreads();
#pragma unroll
        for (int k = 0; k < 16; ++k) {
            float a8[8];
            *(float4*)&a8[0] = *(const float4*)&Xs[k][tx * 8];
            *(float4*)&a8[4] = *(const float4*)&Xs[k][tx * 8 + 4];
            u64 b[4];
            b[0] = *(const u64*)&Ws[k][ty * 8 + 0];
            b[1] = *(const u64*)&Ws[k][ty * 8 + 2];
            b[2] = *(const u64*)&Ws[k][ty * 8 + 4];
            b[3] = *(const u64*)&Ws[k][ty * 8 + 6];
#pragma unroll
            for (int mi = 0; mi < 8; ++mi) {
                const u64 am = fdup(a8[mi]);
                acc[mi][0] = ffma2(am, b[0], acc[mi][0]);
                acc[mi][1] = ffma2(am, b[1], acc[mi][1]);
                acc[mi][2] = ffma2(am, b[2], acc[mi][2]);
                acc[mi][3] = ffma2(am, b[3], acc[mi][3]);
            }
        }
    }

#pragma unroll
    for (int mi = 0; mi < 8; ++mi) {
        float r[8];
#pragma unroll
        for (int jp = 0; jp < 4; ++jp)
            funpack(r[2 * jp], r[2 * jp + 1], acc[mi][jp]);
        float* dst = P + (size_t)(m0 + tx * 8 + mi) * HH + j0 + ty * 8;
        *(float4*)dst       = make_float4(r[0], r[1], r[2], r[3]);
        *(float4*)(dst + 4) = make_float4(r[4], r[5], r[6], r[7]);
    }
}

// ---------------------------------------------------------------------------
// Kernel 2: persistent recurrent scan.  Verbatim R9 EXCEPT the group barrier:
//   release: tid0 atomicAdd with UNUSED return -> REDG (fire-and-forget),
//   wait:    moved to start of next step, tid0 polls with ld.acquire
//            (plain L2 load; acquire replaces the old trailing threadfence).
// Same single-counter-per-group topology proven in R2/R6/R9.
// ---------------------------------------------------------------------------
#define SCAN_SMEM (64*512*4 + 4*512*4 + 8*4*64*4)   // Whs2 + hs + red = 147456

__global__ __launch_bounds__(256, 1) void scan_kernel(
    const float* __restrict__ h0,
    const float* __restrict__ Wh,
    const float* __restrict__ bh,
    float* __restrict__ out,        // (B,S,H): holds P on entry, h_t on exit
    float* __restrict__ hlast)      // (B,H)
{
    extern __shared__ float sm[];
    float* Whs2 = sm;                 // [64 j][512 k], block-swizzled
    float* hs   = sm + 64 * 512;      // [4][512]
    float* red  = hs + 4 * 512;       // [8][4][64]

    const int tid = threadIdx.x;
    const int bg  = blockIdx.x >> 3;     // 0..15
    const int jg  = blockIdx.x & 7;      // 0..7
    const int b0  = bg * BC;
    const int j0  = jg * JC;

    // ---- load Wh slice j-major with block swizzle (once) ----
    {
        const int jl = tid >> 2;             // 0..63
        const int kb = (tid & 3) * 128;      // k chunk base
        const int sw = (jl & 7) << 2;        // word-offset XOR (16B blocks)
        const float* src = Wh + (size_t)(j0 + jl) * HH + kb;
        float* dst = Whs2 + jl * 512;
        for (int kk = 0; kk < 128; kk += 4) {
            float4 v = *(const float4*)(src + kk);
            *(float4*)(dst + ((kb + kk) ^ sw)) = v;
        }
    }

    // compute mapping: warp = k-chunk, lane covers j and j+32, all 4 b's
    const int w     = tid >> 5;          // 0..7 -> k in [w*64, w*64+64)
    const int lane  = tid & 31;
    const int kbase = w * 64;
    const int swz   = (lane & 7) << 2;   // same for j=lane and j=lane+32
    const float* wrow0 = Whs2 + lane * 512;
    const float* wrow1 = Whs2 + (lane + 32) * 512;

    // reduce / output mapping: one thread per output element
    const int rb = tid >> 6;             // 0..3
    const int rj = tid & 63;             // 0..63
    const float bias = bh[j0 + rj];

    // h-load mapping: 4 rows x 512, 8 floats per thread
    const int hrow = tid >> 6;           // 0..3
    const int hk   = (tid & 63) * 8;     // 0..504

    int* ctr = &g_sync[bg];

    __syncthreads();

    for (int t = 0; t < SS; ++t) {
        // prefetch this thread's pre-activation P[b,t,j] (independent of h)
        const size_t oidx = ((size_t)(b0 + rb) * SS + t) * HH + j0 + rj;
        const float pv = __ldcg(out + oidx);

        // ---- wait: all 8 group CTAs finished step t-1 (counter >= 8t) ----
        if (t) {
            if (tid == 0) {
                const int target = NGJ * t;
                while (ld_acq(ctr) < target) { __nanosleep(64); }
            }
            __syncthreads();
        }

        // ---- load h_{t-1} rows into SMEM (bypass L1 for cross-CTA data) ----
        const float* hp = (t == 0)
            ? (h0 + (size_t)(b0 + hrow) * HH + hk)
            : (out + ((size_t)(b0 + hrow) * SS + (t - 1)) * HH + hk);
        float4 hv0 = __ldcg((const float4*)hp);
        float4 hv1 = __ldcg((const float4*)(hp + 4));

        *(float4*)&hs[hrow * 512 + hk]     = hv0;
        *(float4*)&hs[hrow * 512 + hk + 4] = hv1;
        __syncthreads();

        // ---- k-packed f32x2 partial GEMM over this warp's k-chunk ----
        u64 acc[4][2];
#pragma unroll
        for (int b = 0; b < 4; ++b) { acc[b][0] = 0ull; acc[b][1] = 0ull; }

#pragma unroll
        for (int kk = 0; kk < 64; kk += 4) {
            const int k4 = kbase + kk;
            const ulonglong2 wv0 = *(const ulonglong2*)(wrow0 + (k4 ^ swz));
            const ulonglong2 wv1 = *(const ulonglong2*)(wrow1 + (k4 ^ swz));
#pragma unroll
            for (int b = 0; b < 4; ++b) {
                const ulonglong2 hq = *(const ulonglong2*)&hs[b * 512 + k4];
                acc[b][0] = ffma2(hq.x, wv0.x, acc[b][0]);
                acc[b][0] = ffma2(hq.y, wv0.y, acc[b][0]);
                acc[b][1] = ffma2(hq.x, wv1.x, acc[b][1]);
                acc[b][1] = ffma2(hq.y, wv1.y, acc[b][1]);
            }
        }

        // fold (even,odd) halves and publish partials
#pragma unroll
        for (int b = 0; b < 4; ++b) {
            float e0, o0v, e1, o1v;
            funpack(e0, o0v, acc[b][0]);
            funpack(e1, o1v, acc[b][1]);
            red[(w * 4 + b) * 64 + lane]      = e0 + o0v;
            red[(w * 4 + b) * 64 + lane + 32] = e1 + o1v;
        }
        __syncthreads();

        // ---- reduce k-split partials, add P + bias, tanh, write h_t ----
        float sum = pv + bias;
#pragma unroll
        for (int ww = 0; ww < 8; ++ww)
            sum += red[(ww * 4 + rb) * 64 + rj];
        const float hnew = tanhf(sum);
        __stcg(out + oidx, hnew);
        if (t == SS - 1)
            hlast[(size_t)(b0 + rb) * HH + j0 + rj] = hnew;

        // ---- release: h_t visible, then counter += 1 (REDG, no return) ----
        if (t < SS - 1) {
            __threadfence();        // gpu-scope: h stores visible before add
            __syncthreads();        // all threads' stores fenced
            if (tid == 0) atomicAdd(ctr, 1);   // return unused -> RED
        }
    }
}

// ---------------------------------------------------------------------------
extern "C" void kernel_launch(void* const* d_in, const int* in_sizes, int n_in,
                              void* d_out, int out_size) {
    const float* x   = (const float*)d_in[0];   // (B,S,I)
    const float* h0  = (const float*)d_in[1];   // (B,H)
    const float* Wx  = (const float*)d_in[2];   // (H,I)
    const float* Wh  = (const float*)d_in[3];   // (H,H)
    const float* bh  = (const float*)d_in[4];   // (H,)
    float* out   = (float*)d_out;                          // (B,S,H)
    float* hlast = out + (size_t)BB * SS * HH;             // (B,H)

    cudaFuncSetAttribute(scan_kernel,
                         cudaFuncAttributeMaxDynamicSharedMemorySize, SCAN_SMEM);

    reset_kernel<<<1, 32>>>();

    dim3 gg((BB * SS) / 128, HH / 128);   // (1024, 4)
    xproj_kernel<<<gg, 256>>>(x, Wx, out);

    scan_kernel<<<128, 256, SCAN_SMEM>>>(h0, Wh, bh, out, hlast);
}

// round 15
// speedup vs baseline: 2.8992x; 1.0923x over previous
#include <cuda_runtime.h>
#include <math.h>
#include <stdint.h>

#define BB 64
#define SS 2048
#define II 512
#define HH 512

#define NGB 16   // batch groups
#define NGJ 8    // j slices per group
#define BC  4    // batches per group
#define JC  64   // j per slice

typedef unsigned long long u64;

// per-(group,slice) progress flags: value = number of completed steps
__device__ int g_flag[NGB * NGJ];

__global__ void reset_kernel() {
    if (threadIdx.x < NGB * NGJ) g_flag[threadIdx.x] = 0;
}

__device__ __forceinline__ u64 ffma2(u64 a, u64 b, u64 c) {
    u64 d;
    asm("fma.rn.f32x2 %0, %1, %2, %3;" : "=l"(d) : "l"(a), "l"(b), "l"(c));
    return d;
}
__device__ __forceinline__ u64 fdup(float x) {
    u64 d;
    asm("mov.b64 %0, {%1, %1};" : "=l"(d) : "f"(x));
    return d;
}
__device__ __forceinline__ void funpack(float& lo, float& hi, u64 v) {
    asm("mov.b64 {%0, %1}, %2;" : "=f"(lo), "=f"(hi) : "l"(v));
}
__device__ __forceinline__ int ld_acq(const int* p) {
    int v;
    asm volatile("ld.global.acquire.gpu.b32 %0, [%1];" : "=r"(v) : "l"(p));
    return v;
}
__device__ __forceinline__ void red_rel(int* p) {
    asm volatile("red.release.gpu.global.add.u32 [%0], %1;"
                 :: "l"(p), "r"(1) : "memory");
}

// ---------------------------------------------------------------------------
// Kernel 1: xproj GEMM (verbatim R9 — proven).  P[m][j] = sum_i X[m][i]*Wx[j][i]
// 128x128 tile, 256 threads, 8m x 8j per thread via m-packed fma.rn.f32x2.
// ---------------------------------------------------------------------------
__global__ __launch_bounds__(256, 2) void xproj_kernel(
    const float* __restrict__ X,
    const float* __restrict__ Wx,
    float* __restrict__ P)
{
    __shared__ float Xs[16][128];   // [k][m]
    __shared__ float Ws[16][128];   // [k][j]

    const int tid = threadIdx.x;
    const int m0  = blockIdx.x * 128;
    const int j0  = blockIdx.y * 128;
    const int tx  = tid & 15;        // m micro index: rows tx*8..+8
    const int ty  = tid >> 4;        // j micro index: cols ty*8..+8

    const int lrow = tid >> 1;          // 0..127: row to load
    const int lk8  = (tid & 1) * 8;     // 0 or 8: k offset

    const float* xg = X  + (size_t)(m0 + lrow) * II + lk8;
    const float* wg = Wx + (size_t)(j0 + lrow) * II + lk8;

    u64 acc[8][4];
#pragma unroll
    for (int mi = 0; mi < 8; ++mi)
#pragma unroll
        for (int jp = 0; jp < 4; ++jp) acc[mi][jp] = 0ull;

    for (int kc = 0; kc < II; kc += 16) {
        const float4 xa0 = *(const float4*)(xg + kc);
        const float4 xa1 = *(const float4*)(xg + kc + 4);
        const float4 wa0 = *(const float4*)(wg + kc);
        const float4 wa1 = *(const float4*)(wg + kc + 4);
        __syncthreads();
        Xs[lk8 + 0][lrow] = xa0.x; Xs[lk8 + 1][lrow] = xa0.y;
        Xs[lk8 + 2][lrow] = xa0.z; Xs[lk8 + 3][lrow] = xa0.w;
        Xs[lk8 + 4][lrow] = xa1.x; Xs[lk8 + 5][lrow] = xa1.y;
        Xs[lk8 + 6][lrow] = xa1.z; Xs[lk8 + 7][lrow] = xa1.w;
        Ws[lk8 + 0][lrow] = wa0.x; Ws[lk8 + 1][lrow] = wa0.y;
        Ws[lk8 + 2][lrow] = wa0.z; Ws[lk8 + 3][lrow] = wa0.w;
        Ws[lk8 + 4][lrow] = wa1.x; Ws[lk8 + 5][lrow] = wa1.y;
        Ws[lk8 + 6][lrow] = wa1.z; Ws[lk8 + 7][lrow] = wa1.w;
        __syncthreads();
#pragma unroll
        for (int k = 0; k < 16; ++k) {
            float a8[8];
            *(float4*)&a8[0] = *(const float4*)&Xs[k][tx * 8];
            *(float4*)&a8[4] = *(const float4*)&Xs[k][tx * 8 + 4];
            u64 b[4];
            b[0] = *(const u64*)&Ws[k][ty * 8 + 0];
            b[1] = *(const u64*)&Ws[k][ty * 8 + 2];
            b[2] = *(const u64*)&Ws[k][ty * 8 + 4];
            b[3] = *(const u64*)&Ws[k][ty * 8 + 6];
#pragma unroll
            for (int mi = 0; mi < 8; ++mi) {
                const u64 am = fdup(a8[mi]);
                acc[mi][0] = ffma2(am, b[0], acc[mi][0]);
                acc[mi][1] = ffma2(am, b[1], acc[mi][1]);
                acc[mi][2] = ffma2(am, b[2], acc[mi][2]);
                acc[mi][3] = ffma2(am, b[3], acc[mi][3]);
            }
        }
    }

#pragma unroll
    for (int mi = 0; mi < 8; ++mi) {
        float r[8];
#pragma unroll
        for (int jp = 0; jp < 4; ++jp)
            funpack(r[2 * jp], r[2 * jp + 1], acc[mi][jp]);
        float* dst = P + (size_t)(m0 + tx * 8 + mi) * HH + j0 + ty * 8;
        *(float4*)dst       = make_float4(r[0], r[1], r[2], r[3]);
        *(float4*)(dst + 4) = make_float4(r[4], r[5], r[6], r[7]);
    }
}

// ---------------------------------------------------------------------------
// Kernel 2: persistent recurrent scan.  GEMM arithmetic verbatim R14.
// Sync: per-producer flags, per-warp waiting (pipelined exchange).
//   Warp w's k-chunk [64w,+64) is produced by group CTA w.  Lane0 of warp w
//   polls flag[bg][w] with ld.acquire, syncwarp bridges, warp loads ONLY its
//   chunk and computes its partial — detect+load overlaps other warps' GEMMs.
//   Warp jg never waits: its chunk is this CTA's own slice, STS'd into hs by
//   the reduce threads at production time (ordered by the pre-release
//   syncthreads).  Release: tid0 red.release.gpu (cg grid-sync pattern; the
//   bar.sync provides cumulativity, no per-thread threadfence needed).
// ---------------------------------------------------------------------------
#define SCAN_SMEM (64*512*4 + 4*512*4 + 8*4*64*4)   // Whs2 + hs + red = 147456

__global__ __launch_bounds__(256, 1) void scan_kernel(
    const float* __restrict__ h0,
    const float* __restrict__ Wh,
    const float* __restrict__ bh,
    float* __restrict__ out,        // (B,S,H): holds P on entry, h_t on exit
    float* __restrict__ hlast)      // (B,H)
{
    extern __shared__ float sm[];
    float* Whs2 = sm;                 // [64 j][512 k], block-swizzled
    float* hs   = sm + 64 * 512;      // [4][512]
    float* red  = hs + 4 * 512;       // [8][4][64]

    const int tid = threadIdx.x;
    const int bg  = blockIdx.x >> 3;     // 0..15
    const int jg  = blockIdx.x & 7;      // 0..7
    const int b0  = bg * BC;
    const int j0  = jg * JC;

    // ---- load Wh slice j-major with block swizzle (once) ----
    {
        const int jl = tid >> 2;             // 0..63
        const int kb = (tid & 3) * 128;      // k chunk base
        const int sw = (jl & 7) << 2;        // word-offset XOR (16B blocks)
        const float* src = Wh + (size_t)(j0 + jl) * HH + kb;
        float* dst = Whs2 + jl * 512;
        for (int kk = 0; kk < 128; kk += 4) {
            float4 v = *(const float4*)(src + kk);
            *(float4*)(dst + ((kb + kk) ^ sw)) = v;
        }
    }

    // compute mapping: warp = k-chunk, lane covers j and j+32, all 4 b's
    const int w     = tid >> 5;          // 0..7 -> k in [w*64, w*64+64)
    const int lane  = tid & 31;
    const int kbase = w * 64;
    const int swz   = (lane & 7) << 2;   // same for j=lane and j=lane+32
    const float* wrow0 = Whs2 + lane * 512;
    const float* wrow1 = Whs2 + (lane + 32) * 512;

    // per-warp remote-chunk load mapping: 2 rows (hb, hb+2) x 4 floats
    const int hb  = lane >> 4;           // 0/1
    const int k4w = kbase + (lane & 15) * 4;

    // reduce / output mapping: one thread per output element
    const int rb = tid >> 6;             // 0..3
    const int rj = tid & 63;             // 0..63
    const float bias = bh[j0 + rj];
    const size_t obase = (size_t)(b0 + rb) * SS * HH + j0 + rj;

    const int* myflag = &g_flag[bg * NGJ + w];
    int* relflag = &g_flag[bg * NGJ + jg];

    // ---- preload hs from h0 (all regions; warps own disjoint regions after) ----
    {
        const int hrow = tid >> 6;
        const int hk   = (tid & 63) * 8;
        const float* hp = h0 + (size_t)(b0 + hrow) * HH + hk;
        *(float4*)&hs[hrow * 512 + hk]     = *(const float4*)hp;
        *(float4*)&hs[hrow * 512 + hk + 4] = *(const float4*)(hp + 4);
    }
    __syncthreads();

    for (int t = 0; t < SS; ++t) {
        // prefetch this thread's pre-activation P[b,t,j] (independent of h)
        const size_t oidx = obase + (size_t)t * HH;
        const float pv = __ldcg(out + oidx);

        // ---- per-warp acquire of producer w's slice of h_{t-1} ----
        if (t && w != jg) {
            if (lane == 0) {
                while (ld_acq(myflag) < t) { __nanosleep(32); }
            }
            __syncwarp();
            const float* pb = out + ((size_t)(b0 + hb) * SS + (t - 1)) * HH + k4w;
            float4 v0 = __ldcg((const float4*)pb);
            float4 v1 = __ldcg((const float4*)(pb + 2 * (size_t)SS * HH));
            *(float4*)&hs[hb * 512 + k4w]       = v0;
            *(float4*)&hs[(hb + 2) * 512 + k4w] = v1;
            __syncwarp();
        }
        // warp jg: own chunk already in hs (self-written last step, ordered
        // by the pre-release __syncthreads)

        // ---- k-packed f32x2 partial GEMM over this warp's k-chunk ----
        u64 acc[4][2];
#pragma unroll
        for (int b = 0; b < 4; ++b) { acc[b][0] = 0ull; acc[b][1] = 0ull; }

#pragma unroll
        for (int kk = 0; kk < 64; kk += 4) {
            const int k4 = kbase + kk;
            const ulonglong2 wv0 = *(const ulonglong2*)(wrow0 + (k4 ^ swz));
            const ulonglong2 wv1 = *(const ulonglong2*)(wrow1 + (k4 ^ swz));
#pragma unroll
            for (int b = 0; b < 4; ++b) {
                const ulonglong2 hq = *(const ulonglong2*)&hs[b * 512 + k4];
                acc[b][0] = ffma2(hq.x, wv0.x, acc[b][0]);
                acc[b][0] = ffma2(hq.y, wv0.y, acc[b][0]);
                acc[b][1] = ffma2(hq.x, wv1.x, acc[b][1]);
                acc[b][1] = ffma2(hq.y, wv1.y, acc[b][1]);
            }
        }

        // fold (even,odd) halves and publish partials
#pragma unroll
        for (int b = 0; b < 4; ++b) {
            float e0, o0v, e1, o1v;
            funpack(e0, o0v, acc[b][0]);
            funpack(e1, o1v, acc[b][1]);
            red[(w * 4 + b) * 64 + lane]      = e0 + o0v;
            red[(w * 4 + b) * 64 + lane + 32] = e1 + o1v;
        }
        __syncthreads();                       // barrier A

        // ---- reduce k-split partials, add P + bias, tanh, write h_t ----
        float sum = pv + bias;
#pragma unroll
        for (int ww = 0; ww < 8; ++ww)
            sum += red[(ww * 4 + rb) * 64 + rj];
        const float hnew = tanhf(sum);
        __stcg(out + oidx, hnew);              // for remote consumers
        hs[rb * 512 + j0 + rj] = hnew;         // local copy: warp jg's chunk
        if (t == SS - 1)
            hlast[(size_t)(b0 + rb) * HH + j0 + rj] = hnew;

        // ---- release own slice: barrier B orders stores, then RED ----
        if (t < SS - 1) {
            __syncthreads();                   // barrier B
            if (tid == 0) red_rel(relflag);
        }
    }
}

// ---------------------------------------------------------------------------
extern "C" void kernel_launch(void* const* d_in, const int* in_sizes, int n_in,
                              void* d_out, int out_size) {
    const float* x   = (const float*)d_in[0];   // (B,S,I)
    const float* h0  = (const float*)d_in[1];   // (B,H)
    const float* Wx  = (const float*)d_in[2];   // (H,I)
    const float* Wh  = (const float*)d_in[3];   // (H,H)
    const float* bh  = (const float*)d_in[4];   // (H,)
    float* out   = (float*)d_out;                          // (B,S,H)
    float* hlast = out + (size_t)BB * SS * HH;             // (B,H)

    cudaFuncSetAttribute(scan_kernel,
                         cudaFuncAttributeMaxDynamicSharedMemorySize, SCAN_SMEM);

    reset_kernel<<<1, 128>>>();

    dim3 gg((BB * SS) / 128, HH / 128);   // (1024, 4)
    xproj_kernel<<<gg, 256>>>(x, Wx, out);

    scan_kernel<<<128, 256, SCAN_SMEM>>>(h0, Wh, bh, out, hlast);
}

// round 16
// speedup vs baseline: 3.4740x; 1.1982x over previous
#include <cuda_runtime.h>
#include <math.h>
#include <stdint.h>

#define BB 64
#define SS 2048
#define II 512
#define HH 512

#define NGB 16   // batch groups
#define NGJ 8    // j slices per group
#define BC  4    // batches per group
#define JC  64   // j per slice

typedef unsigned long long u64;

// Tagged h exchange: slot = {f32 h (lo 32), u32 step tag (hi 32)}, written
// with one relaxed b64 store (single-copy atomic -> no fences/flags needed).
// Double-buffered by t&1 (overwrite provably cannot outrun readers).
__device__ u64 g_tag[2][NGB][BC][HH];   // 512 KB scratch

__global__ void reset_kernel() {
    const int n = 2 * NGB * BC * HH;    // 65536 slots
    int i = blockIdx.x * blockDim.x + threadIdx.x;
    u64* p = &g_tag[0][0][0][0];
    if (i < n) p[i] = 0xFFFFFFFF00000000ull;   // tag matches no t in [0,2046]
}

__device__ __forceinline__ u64 ffma2(u64 a, u64 b, u64 c) {
    u64 d;
    asm("fma.rn.f32x2 %0, %1, %2, %3;" : "=l"(d) : "l"(a), "l"(b), "l"(c));
    return d;
}
__device__ __forceinline__ u64 fdup(float x) {
    u64 d;
    asm("mov.b64 %0, {%1, %1};" : "=l"(d) : "f"(x));
    return d;
}
__device__ __forceinline__ void funpack(float& lo, float& hi, u64 v) {
    asm("mov.b64 {%0, %1}, %2;" : "=f"(lo), "=f"(hi) : "l"(v));
}
__device__ __forceinline__ u64 ld_rlx(const u64* p) {
    u64 v;
    asm volatile("ld.global.relaxed.gpu.b64 %0, [%1];" : "=l"(v) : "l"(p));
    return v;
}
__device__ __forceinline__ void st_rlx(u64* p, u64 v) {
    asm volatile("st.global.relaxed.gpu.b64 [%0], %1;" :: "l"(p), "l"(v) : "memory");
}
__device__ __forceinline__ u64 pack_ft(float h, unsigned t) {
    u64 d;
    asm("mov.b64 %0, {%1, %2};" : "=l"(d) : "f"(h), "r"(t));
    return d;
}

// ---------------------------------------------------------------------------
// Kernel 1: xproj GEMM (verbatim R9 — proven).  P[m][j] = sum_i X[m][i]*Wx[j][i]
// ---------------------------------------------------------------------------
__global__ __launch_bounds__(256, 2) void xproj_kernel(
    const float* __restrict__ X,
    const float* __restrict__ Wx,
    float* __restrict__ P)
{
    __shared__ float Xs[16][128];   // [k][m]
    __shared__ float Ws[16][128];   // [k][j]

    const int tid = threadIdx.x;
    const int m0  = blockIdx.x * 128;
    const int j0  = blockIdx.y * 128;
    const int tx  = tid & 15;
    const int ty  = tid >> 4;

    const int lrow = tid >> 1;
    const int lk8  = (tid & 1) * 8;

    const float* xg = X  + (size_t)(m0 + lrow) * II + lk8;
    const float* wg = Wx + (size_t)(j0 + lrow) * II + lk8;

    u64 acc[8][4];
#pragma unroll
    for (int mi = 0; mi < 8; ++mi)
#pragma unroll
        for (int jp = 0; jp < 4; ++jp) acc[mi][jp] = 0ull;

    for (int kc = 0; kc < II; kc += 16) {
        const float4 xa0 = *(const float4*)(xg + kc);
        const float4 xa1 = *(const float4*)(xg + kc + 4);
        const float4 wa0 = *(const float4*)(wg + kc);
        const float4 wa1 = *(const float4*)(wg + kc + 4);
        __syncthreads();
        Xs[lk8 + 0][lrow] = xa0.x; Xs[lk8 + 1][lrow] = xa0.y;
        Xs[lk8 + 2][lrow] = xa0.z; Xs[lk8 + 3][lrow] = xa0.w;
        Xs[lk8 + 4][lrow] = xa1.x; Xs[lk8 + 5][lrow] = xa1.y;
        Xs[lk8 + 6][lrow] = xa1.z; Xs[lk8 + 7][lrow] = xa1.w;
        Ws[lk8 + 0][lrow] = wa0.x; Ws[lk8 + 1][lrow] = wa0.y;
        Ws[lk8 + 2][lrow] = wa0.z; Ws[lk8 + 3][lrow] = wa0.w;
        Ws[lk8 + 4][lrow] = wa1.x; Ws[lk8 + 5][lrow] = wa1.y;
        Ws[lk8 + 6][lrow] = wa1.z; Ws[lk8 + 7][lrow] = wa1.w;
        __syncthreads();
#pragma unroll
        for (int k = 0; k < 16; ++k) {
            float a8[8];
            *(float4*)&a8[0] = *(const float4*)&Xs[k][tx * 8];
            *(float4*)&a8[4] = *(const float4*)&Xs[k][tx * 8 + 4];
            u64 b[4];
            b[0] = *(const u64*)&Ws[k][ty * 8 + 0];
            b[1] = *(const u64*)&Ws[k][ty * 8 + 2];
            b[2] = *(const u64*)&Ws[k][ty * 8 + 4];
            b[3] = *(const u64*)&Ws[k][ty * 8 + 6];
#pragma unroll
            for (int mi = 0; mi < 8; ++mi) {
                const u64 am = fdup(a8[mi]);
                acc[mi][0] = ffma2(am, b[0], acc[mi][0]);
                acc[mi][1] = ffma2(am, b[1], acc[mi][1]);
                acc[mi][2] = ffma2(am, b[2], acc[mi][2]);
                acc[mi][3] = ffma2(am, b[3], acc[mi][3]);
            }
        }
    }

#pragma unroll
    for (int mi = 0; mi < 8; ++mi) {
        float r[8];
#pragma unroll
        for (int jp = 0; jp < 4; ++jp)
            funpack(r[2 * jp], r[2 * jp + 1], acc[mi][jp]);
        float* dst = P + (size_t)(m0 + tx * 8 + mi) * HH + j0 + ty * 8;
        *(float4*)dst       = make_float4(r[0], r[1], r[2], r[3]);
        *(float4*)(dst + 4) = make_float4(r[4], r[5], r[6], r[7]);
    }
}

// ---------------------------------------------------------------------------
// Kernel 2: persistent recurrent scan.  GEMM arithmetic verbatim R15.
// Exchange: tagged-value single-RTT protocol.
//   Producer thread (rb,rj): one st.relaxed.b64 {h, t} into g_tag[t&1].
//   Consumer warp w polls its 256-value chunk (8 slots/lane) until tag==t-1;
//   retry loop is self-paced at ~1 L2 RTT.  No fences, no flags, no
//   barrier B; red[] ping-pong makes the single barrier A sufficient
//   (STS(t+2) is ordered after barrier A(t+1) after all reduce(t) reads).
//   hs is warp-private (each warp, incl. w==jg, fills its own k-chunk).
// ---------------------------------------------------------------------------
#define SCAN_SMEM (64*512*4 + 4*512*4 + 2*8*4*64*4)   // Whs2 + hs + red[2] = 155648

__global__ __launch_bounds__(256, 1) void scan_kernel(
    const float* __restrict__ h0,
    const float* __restrict__ Wh,
    const float* __restrict__ bh,
    float* __restrict__ out,        // (B,S,H): holds P on entry, h_t on exit
    float* __restrict__ hlast)      // (B,H)
{
    extern __shared__ float sm[];
    float* Whs2 = sm;                 // [64 j][512 k], block-swizzled
    float* hs   = sm + 64 * 512;      // [4][512] (warp-private k-columns)
    float* red  = hs + 4 * 512;       // [2][8][4][64] ping-pong partials

    const int tid = threadIdx.x;
    const int bg  = blockIdx.x >> 3;     // 0..15
    const int jg  = blockIdx.x & 7;      // 0..7
    const int b0  = bg * BC;
    const int j0  = jg * JC;

    // ---- load Wh slice j-major with block swizzle (once) ----
    {
        const int jl = tid >> 2;             // 0..63
        const int kb = (tid & 3) * 128;      // k chunk base
        const int sw = (jl & 7) << 2;        // word-offset XOR (16B blocks)
        const float* src = Wh + (size_t)(j0 + jl) * HH + kb;
        float* dst = Whs2 + jl * 512;
        for (int kk = 0; kk < 128; kk += 4) {
            float4 v = *(const float4*)(src + kk);
            *(float4*)(dst + ((kb + kk) ^ sw)) = v;
        }
    }

    // compute mapping: warp = k-chunk, lane covers j and j+32, all 4 b's
    const int w     = tid >> 5;          // 0..7 -> k in [w*64, w*64+64)
    const int lane  = tid & 31;
    const int kbase = w * 64;
    const int swz   = (lane & 7) << 2;
    const float* wrow0 = Whs2 + lane * 512;
    const float* wrow1 = Whs2 + (lane + 32) * 512;

    // consumer chunk mapping: lane -> rows {hb, hb+2}, 4 slots each
    const int hb  = lane >> 4;           // 0/1
    const int k4w = kbase + (lane & 15) * 4;

    // reduce / output mapping: one thread per output element
    const int rb = tid >> 6;             // 0..3
    const int rj = tid & 63;             // 0..63
    const float bias = bh[j0 + rj];
    const size_t obase = (size_t)(b0 + rb) * SS * HH + j0 + rj;

    // ---- preload hs from h0 ----
    {
        const int hrow = tid >> 6;
        const int hk   = (tid & 63) * 8;
        const float* hp = h0 + (size_t)(b0 + hrow) * HH + hk;
        *(float4*)&hs[hrow * 512 + hk]     = *(const float4*)hp;
        *(float4*)&hs[hrow * 512 + hk + 4] = *(const float4*)(hp + 4);
    }
    __syncthreads();

    for (int t = 0; t < SS; ++t) {
        // prefetch this thread's pre-activation P[b,t,j] (independent of h)
        const size_t oidx = obase + (size_t)t * HH;
        const float pv = __ldcg(out + oidx);

        // ---- tagged-value acquire of this warp's h_{t-1} chunk ----
        if (t) {
            const u64* gt = &g_tag[(t - 1) & 1][bg][0][0];
            const u64* a0 = gt + (size_t)hb * HH + k4w;
            const u64* a1 = gt + (size_t)(hb + 2) * HH + k4w;
            const unsigned want = (unsigned)(t - 1);
            u64 got[8];
            unsigned need = 0xFFu;
            while (need) {
#pragma unroll
                for (int i = 0; i < 4; ++i)
                    if (need & (1u << i)) got[i] = ld_rlx(a0 + i);
#pragma unroll
                for (int i = 0; i < 4; ++i)
                    if (need & (1u << (4 + i))) got[4 + i] = ld_rlx(a1 + i);
#pragma unroll
                for (int i = 0; i < 8; ++i)
                    if ((need & (1u << i)) && (unsigned)(got[i] >> 32) == want)
                        need &= ~(1u << i);
            }
            float f[8];
#pragma unroll
            for (int i = 0; i < 8; ++i)
                f[i] = __uint_as_float((unsigned)(got[i] & 0xFFFFFFFFu));
            *(float4*)&hs[hb * 512 + k4w]       = make_float4(f[0], f[1], f[2], f[3]);
            *(float4*)&hs[(hb + 2) * 512 + k4w] = make_float4(f[4], f[5], f[6], f[7]);
            __syncwarp();
        }

        // ---- k-packed f32x2 partial GEMM over this warp's k-chunk ----
        u64 acc[4][2];
#pragma unroll
        for (int b = 0; b < 4; ++b) { acc[b][0] = 0ull; acc[b][1] = 0ull; }

#pragma unroll
        for (int kk = 0; kk < 64; kk += 4) {
            const int k4 = kbase + kk;
            const ulonglong2 wv0 = *(const ulonglong2*)(wrow0 + (k4 ^ swz));
            const ulonglong2 wv1 = *(const ulonglong2*)(wrow1 + (k4 ^ swz));
#pragma unroll
            for (int b = 0; b < 4; ++b) {
                const ulonglong2 hq = *(const ulonglong2*)&hs[b * 512 + k4];
                acc[b][0] = ffma2(hq.x, wv0.x, acc[b][0]);
                acc[b][0] = ffma2(hq.y, wv0.y, acc[b][0]);
                acc[b][1] = ffma2(hq.x, wv1.x, acc[b][1]);
                acc[b][1] = ffma2(hq.y, wv1.y, acc[b][1]);
            }
        }

        // fold (even,odd) halves and publish partials (ping-pong buffer)
        float* rbuf = red + (t & 1) * 2048;
#pragma unroll
        for (int b = 0; b < 4; ++b) {
            float e0, o0v, e1, o1v;
            funpack(e0, o0v, acc[b][0]);
            funpack(e1, o1v, acc[b][1]);
            rbuf[(w * 4 + b) * 64 + lane]      = e0 + o0v;
            rbuf[(w * 4 + b) * 64 + lane + 32] = e1 + o1v;
        }
        __syncthreads();                       // barrier A (only barrier/step)

        // ---- reduce k-split partials, add P + bias, tanh, write h_t ----
        float sum = pv + bias;
#pragma unroll
        for (int ww = 0; ww < 8; ++ww)
            sum += rbuf[(ww * 4 + rb) * 64 + rj];
        const float hnew = tanhf(sum);
        __stcg(out + oidx, hnew);              // final output value
        if (t == SS - 1) {
            hlast[(size_t)(b0 + rb) * HH + j0 + rj] = hnew;
        } else {
            // tagged release: data+tag in one atomic 8B store
            st_rlx(&g_tag[t & 1][bg][rb][j0 + rj], pack_ft(hnew, (unsigned)t));
        }
    }
}

// ---------------------------------------------------------------------------
extern "C" void kernel_launch(void* const* d_in, const int* in_sizes, int n_in,
                              void* d_out, int out_size) {
    const float* x   = (const float*)d_in[0];   // (B,S,I)
    const float* h0  = (const float*)d_in[1];   // (B,H)
    const float* Wx  = (const float*)d_in[2];   // (H,I)
    const float* Wh  = (const float*)d_in[3];   // (H,H)
    const float* bh  = (const float*)d_in[4];   // (H,)
    float* out   = (float*)d_out;                          // (B,S,H)
    float* hlast = out + (size_t)BB * SS * HH;             // (B,H)

    cudaFuncSetAttribute(scan_kernel,
                         cudaFuncAttributeMaxDynamicSharedMemorySize, SCAN_SMEM);

    reset_kernel<<<256, 256>>>();

    dim3 gg((BB * SS) / 128, HH / 128);   // (1024, 4)
    xproj_kernel<<<gg, 256>>>(x, Wx, out);

    scan_kernel<<<128, 256, SCAN_SMEM>>>(h0, Wh, bh, out, hlast);
}